// round 17
// baseline (speedup 1.0000x reference)
#include <cuda_runtime.h>

// ---------------------------------------------------------------------------
// 6-qubit, 3-layer circuit, B=131072. TWO threads per state (t = q0), each
// holding 16 packed-f32x2 real + 16 imag regs (lane = q5; pack bits
// 3..0 = q1,q2,q3,q4).
//  * Layer-1 CNOT ring + its q0,q1 gates absorbed analytically into build.
//  * Layer-1 q2,q3,q4 gates absorbed into the build's tensor stages.
//  * Build's head (T/W/P/V) lane-packed over y5 (f32x2 throughout).
//  * Layer-1 q5 gate: local packed butterfly (lane).
//  * Layer 2: C01 = t-predicated SELs; C12/C23/C34 renames; C45+C50+U0
//    realized via LANE-MIXED PACKED COEFFICIENTS (no data repacking movs):
//      even p: R' = cLR.LR + cLI.LI + cMR.MR + cMI.MI
//              I' = dLR.LR + cLR.LI + dMR.MR + cMR.MI
//      odd  p: same with all four inputs f2swap'ed.
//    q1..q5 local butterflies.
//  * Layer 3: C01 SELs + C12/C23/C34 renames; C45, C50 and all six gates
//    absorbed into observables (Heisenberg). X45 single-sided (2x in g_m).
// ---------------------------------------------------------------------------

typedef unsigned long long u64;
#define SGN2 0x8000000080000000ULL
#define SHI  0x8000000000000000ULL
#define SLO  0x0000000080000000ULL

__device__ __forceinline__ u64 pk2(float a, float b) {
    u64 r; asm("mov.b64 %0,{%1,%2};" : "=l"(r) : "f"(a), "f"(b)); return r;
}
__device__ __forceinline__ void upk2(u64 v, float& a, float& b) {
    asm("mov.b64 {%0,%1},%2;" : "=f"(a), "=f"(b) : "l"(v));
}
__device__ __forceinline__ u64 bc2(float a) { return pk2(a, a); }
__device__ __forceinline__ u64 f2mul(u64 a, u64 b) {
    u64 d; asm("mul.rn.f32x2 %0,%1,%2;" : "=l"(d) : "l"(a), "l"(b)); return d;
}
__device__ __forceinline__ u64 f2fma(u64 a, u64 b, u64 c) {
    u64 d; asm("fma.rn.f32x2 %0,%1,%2,%3;" : "=l"(d) : "l"(a), "l"(b), "l"(c)); return d;
}
__device__ __forceinline__ u64 f2add(u64 a, u64 b) {
    u64 d; asm("add.rn.f32x2 %0,%1,%2;" : "=l"(d) : "l"(a), "l"(b)); return d;
}
__device__ __forceinline__ u64 f2swap(u64 a) {
    u64 d;
    asm("{\n\t.reg .b32 x,y;\n\tmov.b64 {x,y},%1;\n\tmov.b64 %0,{y,x};\n\t}"
        : "=l"(d) : "l"(a));
    return d;
}

// g_u[40..45]: layer-1 q5 table.
// g_u[48..95]: layer-2 table: q0 at +0 = 6 lane-mixed packed coefs
//   [pk2(ar,br), pk2(-ai,-bi), pk2(br,ar), pk2(-bi,-ai), pk2(ai,bi),
//    pk2(bi,ai)]; q1..q4 at +8/+16/+24/+32 [ar,ai,-ai,br,-br,bi,-bi];
//   q5 at +40.
__device__ u64 g_u[2 * 48];
// Layer-1 q0..q4 raw SU(2) coefficients: [q*4] = ar, ai, br, bi
__device__ float g_l1[20];
// Observable combine constants per qubit: [cx, cy, cz, pad]
__device__ float g_m[24];

__global__ void prep_kernel(const float* __restrict__ theta) {
    int t = threadIdx.x;
    if (t < 18) {
        int l = t / 6, q = t % 6;
        const float* th = theta + t * 3;
        float sx, cx, sy, cy, sz, cz;
        __sincosf(th[0] * 0.5f, &sx, &cx);
        __sincosf(th[1] * 0.5f, &sy, &cy);
        __sincosf(th[2] * 0.5f, &sz, &cz);
        float m00r =  cy * cx, m00i =  sy * sx;
        float m01r = -sy * cx, m01i = -cy * sx;
        float ar = cz * m00r + sz * m00i, ai = cz * m00i - sz * m00r;
        float br = cz * m01r + sz * m01i, bi = cz * m01i - sz * m01r;
        if (l == 0) {
            if (q <= 4) {
                g_l1[q * 4 + 0] = ar; g_l1[q * 4 + 1] = ai;
                g_l1[q * 4 + 2] = br; g_l1[q * 4 + 3] = bi;
            } else {
                u64* h = g_u + 40;
                h[0] = pk2(ar, ar);   h[1] = pk2(-ai, ai);
                h[2] = pk2(br, -br);  h[3] = pk2(-bi, -bi);
                h[4] = pk2(ai, -ai);  h[5] = pk2(bi, bi);
            }
        } else if (l == 1) {
            u64* g = g_u + 48;
            if (q == 0) {
                // lane-mixed packed coefs for the C45/C50-folded q0 gate
                g[0] = pk2(ar, br);   g[1] = pk2(-ai, -bi);
                g[2] = pk2(br, ar);   g[3] = pk2(-bi, -ai);
                g[4] = pk2(ai, bi);   g[5] = pk2(bi, ai);
            } else if (q < 5) {
                u64* h = g + 8 + (q - 1) * 8;
                h[0] = bc2(ar); h[1] = bc2(ai); h[2] = bc2(-ai);
                h[3] = bc2(br); h[4] = bc2(-br); h[5] = bc2(bi); h[6] = bc2(-bi);
            } else {
                u64* h = g + 40;
                h[0] = pk2(ar, ar);   h[1] = pk2(-ai, ai);
                h[2] = pk2(br, -br);  h[3] = pk2(-bi, -bi);
                h[4] = pk2(ai, -ai);  h[5] = pk2(bi, bi);
            }
        } else {
            // layer 3 observable n-vector. even q: U†ZU, odd q: U†XU
            float nx, ny, nz;
            if ((q & 1) == 0) {
                nz = (ar * ar + ai * ai) - (br * br + bi * bi);
                nx = 2.0f * (br * ar + bi * ai);
                ny = 2.0f * (br * ai - bi * ar);
            } else {
                nz = -2.0f * (ar * br - ai * bi);
                nx = ar * ar - ai * ai - br * br + bi * bi;
                ny = 2.0f * (ar * ai + br * bi);
            }
            if (q == 1 || q == 2 || q == 3) { nx *= 2.0f; ny *= 2.0f; }
            if (q == 4) { nx *= 2.0f; ny *= 2.0f; }  // X45 single-sided
            g_m[q * 4 + 0] = nx;
            g_m[q * 4 + 1] = ny;
            g_m[q * 4 + 2] = nz;
        }
    }
}

// Local SU(2) on pack bit (MP = 8 -> q1, 4 -> q2, 2 -> q3, 1 -> q4).
template <int MP>
__device__ __forceinline__ void su2_loc(u64* R, u64* I, const u64* __restrict__ u) {
    u64 ar = u[0], ai = u[1], nai = u[2];
    u64 br = u[3], nbr = u[4], bi = u[5], nbi = u[6];
#pragma unroll
    for (int g = 0; g < 8; g++) {
        int p0 = (g & (MP - 1)) | ((g & ~(MP - 1)) << 1);
        int p1 = p0 | MP;
        u64 Ar = R[p0], Ai = I[p0], Br = R[p1], Bi = I[p1];
        R[p0] = f2fma(nbi, Bi, f2fma(br, Br, f2fma(nai, Ai, f2mul(ar, Ar))));
        I[p0] = f2fma(br, Bi, f2fma(bi, Br, f2fma(ai, Ar, f2mul(ar, Ai))));
        R[p1] = f2fma(ai, Bi, f2fma(ar, Br, f2fma(nbi, Ai, f2mul(nbr, Ar))));
        I[p1] = f2fma(nai, Br, f2fma(ar, Bi, f2fma(bi, Ar, f2mul(nbr, Ai))));
    }
}

// Local SU(2) on qubit 5 (lane), within-pack butterfly via half-swap.
__device__ __forceinline__ void su2_q5(u64* R, u64* I, const u64* __restrict__ u) {
    u64 aa = u[0], am = u[1], bp = u[2], nb2 = u[3], ap = u[4], bb = u[5];
#pragma unroll
    for (int p = 0; p < 16; p++) {
        u64 r = R[p], m = I[p];
        u64 sr = f2swap(r), sm = f2swap(m);
        R[p] = f2fma(nb2, sm, f2fma(bp, sr, f2fma(am, m, f2mul(aa, r))));
        I[p] = f2fma(bb, sr, f2fma(bp, sm, f2fma(ap, r, f2mul(aa, m))));
    }
}

__device__ __forceinline__ void swp(u64* A, int i, int j) {
    u64 t = A[i]; A[i] = A[j]; A[j] = t;
}

// CNOT(1,2),(2,3),(3,4) as register renames on the 16-pack array.
__device__ __forceinline__ void cnot_ring_mid(u64* R, u64* I) {
    swp(R, 8, 12); swp(R, 9, 13); swp(R, 10, 14); swp(R, 11, 15);
    swp(I, 8, 12); swp(I, 9, 13); swp(I, 10, 14); swp(I, 11, 15);
    swp(R, 4, 6); swp(R, 5, 7); swp(R, 12, 14); swp(R, 13, 15);
    swp(I, 4, 6); swp(I, 5, 7); swp(I, 12, 14); swp(I, 13, 15);
    swp(R, 2, 3); swp(R, 6, 7); swp(R, 10, 11); swp(R, 14, 15);
    swp(I, 2, 3); swp(I, 6, 7); swp(I, 10, 11); swp(I, 14, 15);
}

// CNOT(0,1): control = thread bit, target = pack bit3 (predicated SELs).
__device__ __forceinline__ void cnot01(u64* R, u64* I, bool c) {
#pragma unroll
    for (int p = 0; p < 8; p++) {
        u64 a = R[p], b = R[p + 8];
        R[p] = c ? b : a;  R[p + 8] = c ? a : b;
        a = I[p]; b = I[p + 8];
        I[p] = c ? b : a;  I[p + 8] = c ? a : b;
    }
}

__global__ __launch_bounds__(128, 5) void qsim_kernel(
    const float* __restrict__ x, float* __restrict__ out, int Bn)
{
    int gid = blockIdx.x * 128 + threadIdx.x;
    int st = gid >> 1;
    if (st >= Bn) return;
    int t = gid & 1;

    // --- encoding (1 sincos per qubit; double-angle for a/2 terms) ---
    const float4* x4 = reinterpret_cast<const float4*>(x) + (long)st * 6;
    float ur[6][2], ui[6][2];
#pragma unroll
    for (int q = 0; q < 6; q++) {
        float4 v = __ldg(&x4[q]);
        float a = (v.x + v.y + v.z + v.w) * 0.25f;
        a = fminf(6.0f, fmaxf(-6.0f, a)) * (3.14159265358979323846f / 6.0f);
        float s4, c4;
        __sincosf(a * 0.25f, &s4, &c4);
        float s2 = 2.0f * s4 * c4;
        float c2 = fmaf(-2.0f * s4, s4, 1.0f);
        ur[q][0] = c2 * c4;  ui[q][0] = -c2 * s4;
        ur[q][1] = s2 * s4;  ui[q][1] = -s2 * c4;
    }

    // --- build head, lane-packed over y5: T -> W -> P -> V ---
    u64 VR[2][2], VI[2][2];  // [y1][y2o], lane = y5
    {
        float C0r, C0i, C1r, C1i;
        {
            float a0r = g_l1[0], a0i = g_l1[1], b0r = g_l1[2], b0i = g_l1[3];
            C0r = t ? -b0r : a0r;  C0i = t ?  b0i : a0i;
            C1r = t ?  a0r : b0r;  C1i = t ? -a0i : b0i;
        }
        u64 U0R = pk2(ur[0][0], ur[0][1]), U0I = pk2(ui[0][0], ui[0][1]);
        u64 U1R = pk2(ur[1][0], ur[1][1]), U1I = pk2(ui[1][0], ui[1][1]);
        u64 sU0R = f2swap(U0R), sU0I = f2swap(U0I);
        u64 sU1R = f2swap(U1R), sU1I = f2swap(U1I);
        u64 cC0r = bc2(C0r), cC0i = bc2(C0i), nC0i = cC0i ^ SGN2;
        u64 cC1r = bc2(C1r), cC1i = bc2(C1i), nC1i = cC1i ^ SGN2;
        u64 T0R = f2fma(nC0i, U0I, f2mul(cC0r, U0R));
        u64 T0I = f2fma(cC0i, U0R, f2mul(cC0r, U0I));
        u64 T1R = f2fma(nC1i, sU0I, f2mul(cC1r, sU0R));
        u64 T1I = f2fma(cC1i, sU0R, f2mul(cC1r, sU0I));
        u64 nT0I = T0I ^ SGN2, nT1I = T1I ^ SGN2;
        u64 W0R = f2fma(nT1I, sU1I, f2fma(T1R, sU1R, f2fma(nT0I, U1I, f2mul(T0R, U1R))));
        u64 W0I = f2fma(T1I, sU1R, f2fma(T1R, sU1I, f2fma(T0I, U1R, f2mul(T0R, U1I))));
        u64 W1R = f2fma(nT1I, U1I, f2fma(T1R, U1R, f2fma(nT0I, sU1I, f2mul(T0R, sU1R))));
        u64 W1I = f2fma(T1I, U1R, f2fma(T1R, U1I, f2fma(T0I, sU1R, f2mul(T0R, sU1I))));
        u64 cA1r = bc2(g_l1[4]), cA1i = bc2(g_l1[5]), nA1i = cA1i ^ SGN2;
        u64 cB1r = bc2(g_l1[6]), cB1i = bc2(g_l1[7]), nB1i = cB1i ^ SGN2;
        u64 nB1r = cB1r ^ SGN2;
        u64 P00R = f2fma(nA1i, W0I, f2mul(cA1r, W0R));
        u64 P00I = f2fma(cA1i, W0R, f2mul(cA1r, W0I));
        u64 P01R = f2fma(nB1i, W1I, f2mul(cB1r, W1R));
        u64 P01I = f2fma(cB1i, W1R, f2mul(cB1r, W1I));
        u64 P10R = f2fma(nB1i, W0I, f2mul(nB1r, W0R));
        u64 P10I = f2fma(cB1i, W0R, f2mul(nB1r, W0I));
        u64 P11R = f2fma(cA1i, W1I, f2mul(cA1r, W1R));
        u64 P11I = f2fma(nA1i, W1R, f2mul(cA1r, W1I));
        u64 u2r0 = bc2(ur[2][0]), u2r1 = bc2(ur[2][1]);
        u64 u2i0 = bc2(ui[2][0]), u2i1 = bc2(ui[2][1]);
        u64 n2i0 = u2i0 ^ SGN2, n2i1 = u2i1 ^ SGN2;
        VR[0][0] = f2fma(n2i1, P01I, f2fma(u2r1, P01R, f2fma(n2i0, P00I, f2mul(u2r0, P00R))));
        VI[0][0] = f2fma(u2i1, P01R, f2fma(u2r1, P01I, f2fma(u2i0, P00R, f2mul(u2r0, P00I))));
        VR[0][1] = f2fma(n2i0, P01I, f2fma(u2r0, P01R, f2fma(n2i1, P00I, f2mul(u2r1, P00R))));
        VI[0][1] = f2fma(u2i0, P01R, f2fma(u2r0, P01I, f2fma(u2i1, P00R, f2mul(u2r1, P00I))));
        VR[1][0] = f2fma(n2i1, P11I, f2fma(u2r1, P11R, f2fma(n2i0, P10I, f2mul(u2r0, P10R))));
        VI[1][0] = f2fma(u2i1, P11R, f2fma(u2r1, P11I, f2fma(u2i0, P10R, f2mul(u2r0, P10I))));
        VR[1][1] = f2fma(n2i0, P11I, f2fma(u2r0, P11R, f2fma(n2i1, P10I, f2mul(u2r1, P10R))));
        VI[1][1] = f2fma(u2i0, P11R, f2fma(u2r0, P11I, f2fma(u2i1, P10R, f2mul(u2r1, P10I))));
    }

    // --- K tables with layer-1 U4 and U3 folded in ---
    u64 TKR[2][2][2], TKI[2][2][2];   // K~[y3][y3o][y4]
    {
        float k45r[2][2], k45i[2][2];
#pragma unroll
        for (int m = 0; m < 2; m++)
#pragma unroll
            for (int n = 0; n < 2; n++) {
                k45r[m][n] = ur[4][m] * ur[5][n] - ui[4][m] * ui[5][n];
                k45i[m][n] = ur[4][m] * ui[5][n] + ui[4][m] * ur[5][n];
            }
        u64 A4r = bc2(g_l1[16]), A4i = bc2(g_l1[17]);
        u64 B4r = bc2(g_l1[18]), B4i = bc2(g_l1[19]);
        u64 A3r = bc2(g_l1[12]), A3i = bc2(g_l1[13]);
        u64 B3r = bc2(g_l1[14]), B3i = bc2(g_l1[15]);
#pragma unroll
        for (int y3o = 0; y3o < 2; y3o++) {
            int m0 = 0 ^ y3o, m1 = 1 ^ y3o;
            u64 r0 = pk2(k45r[m0][0], k45r[m0][1]);
            u64 i0 = pk2(k45i[m0][0], k45i[m0][1]);
            u64 r1 = pk2(k45r[m1][1], k45r[m1][0]);
            u64 i1 = pk2(k45i[m1][1], k45i[m1][0]);
            u64 K40R = f2fma(B4i ^ SGN2, i1, f2fma(B4r, r1,
                        f2fma(A4i ^ SGN2, i0, f2mul(A4r, r0))));
            u64 K40I = f2fma(B4i, r1, f2fma(B4r, i1,
                        f2fma(A4i, r0, f2mul(A4r, i0))));
            u64 K41R = f2fma(A4i, i1, f2fma(A4r, r1,
                        f2fma(B4i ^ SGN2, i0, f2mul(B4r ^ SGN2, r0))));
            u64 K41I = f2fma(A4i ^ SGN2, r1, f2fma(A4r, i1,
                        f2fma(B4i, r0, f2mul(B4r ^ SGN2, i0))));
            u64 cr0, ci0, cr1, ci1;
            if (y3o == 0) { cr0 = A3r; ci0 = A3i; cr1 = B3r ^ SGN2; ci1 = B3i; }
            else          { cr0 = B3r; ci0 = B3i; cr1 = A3r; ci1 = A3i ^ SGN2; }
            TKR[0][y3o][0] = f2fma(ci0 ^ SGN2, K40I, f2mul(cr0, K40R));
            TKI[0][y3o][0] = f2fma(ci0, K40R, f2mul(cr0, K40I));
            TKR[0][y3o][1] = f2fma(ci0 ^ SGN2, K41I, f2mul(cr0, K41R));
            TKI[0][y3o][1] = f2fma(ci0, K41R, f2mul(cr0, K41I));
            TKR[1][y3o][0] = f2fma(ci1 ^ SGN2, K40I, f2mul(cr1, K40R));
            TKI[1][y3o][0] = f2fma(ci1, K40R, f2mul(cr1, K40I));
            TKR[1][y3o][1] = f2fma(ci1 ^ SGN2, K41I, f2mul(cr1, K41R));
            TKI[1][y3o][1] = f2fma(ci1, K41R, f2mul(cr1, K41I));
        }
    }

    // --- CRm (with U2 folded) and expansion via K~ ---
    u64 R[16], I[16];
    {
        u64 w3r[2], w3i[2], n3i[2];
        w3r[0] = bc2(ur[3][0]); w3i[0] = bc2(ui[3][0]); n3i[0] = w3i[0] ^ SGN2;
        w3r[1] = bc2(ur[3][1]); w3i[1] = bc2(ui[3][1]); n3i[1] = w3i[1] ^ SGN2;
        u64 A2r = bc2(g_l1[8]),  A2i = bc2(g_l1[9]);
        u64 B2r = bc2(g_l1[10]), B2i = bc2(g_l1[11]);
#pragma unroll
        for (int y1 = 0; y1 < 2; y1++) {
            u64 c0R[2], c0I[2], c1R[2], c1I[2];
            {
                u64 BR = VR[y1][0], BI = VI[y1][0];
#pragma unroll
                for (int y3o = 0; y3o < 2; y3o++) {
                    int m = y3o;
                    c0R[y3o] = f2fma(n3i[m], BI, f2mul(w3r[m], BR));
                    c0I[y3o] = f2fma(w3i[m], BR, f2mul(w3r[m], BI));
                }
                BR = VR[y1][1]; BI = VI[y1][1];
#pragma unroll
                for (int y3o = 0; y3o < 2; y3o++) {
                    int m = 1 ^ y3o;
                    c1R[y3o] = f2fma(n3i[m], BI, f2mul(w3r[m], BR));
                    c1I[y3o] = f2fma(w3i[m], BR, f2mul(w3r[m], BI));
                }
            }
            u64 DR[2][2], DI[2][2];
#pragma unroll
            for (int y3o = 0; y3o < 2; y3o++) {
                u64 r0 = c0R[y3o], i0 = c0I[y3o];
                u64 r1 = c1R[y3o], i1 = c1I[y3o];
                DR[0][y3o] = f2fma(B2i ^ SGN2, i1, f2fma(B2r, r1,
                              f2fma(A2i ^ SGN2, i0, f2mul(A2r, r0))));
                DI[0][y3o] = f2fma(B2i, r1, f2fma(B2r, i1,
                              f2fma(A2i, r0, f2mul(A2r, i0))));
                DR[1][y3o] = f2fma(A2i, i1, f2fma(A2r, r1,
                              f2fma(B2i ^ SGN2, i0, f2mul(B2r ^ SGN2, r0))));
                DI[1][y3o] = f2fma(A2i ^ SGN2, r1, f2fma(A2r, i1,
                              f2fma(B2i, r0, f2mul(B2r ^ SGN2, i0))));
            }
#pragma unroll
            for (int y2 = 0; y2 < 2; y2++) {
                u64 xr0 = DR[y2][0], xi0 = DI[y2][0];
                u64 xr1 = DR[y2][1], xi1 = DI[y2][1];
                u64 nxi0 = xi0 ^ SGN2, nxi1 = xi1 ^ SGN2;
#pragma unroll
                for (int y3 = 0; y3 < 2; y3++)
#pragma unroll
                    for (int y4 = 0; y4 < 2; y4++) {
                        int p = (y1 << 3) | (y2 << 2) | (y3 << 1) | y4;
                        R[p] = f2fma(nxi1, TKI[y3][1][y4], f2fma(xr1, TKR[y3][1][y4],
                                f2fma(nxi0, TKI[y3][0][y4], f2mul(xr0, TKR[y3][0][y4]))));
                        I[p] = f2fma(xi1, TKR[y3][1][y4], f2fma(xr1, TKI[y3][1][y4],
                                f2fma(xi0, TKR[y3][0][y4], f2mul(xr0, TKI[y3][0][y4]))));
                    }
            }
        }
    }

    // --- layer-1 q5 gate (lane) ---
    su2_q5(R, I, g_u + 40);

    // --- layer 2 (full) ---
    {
        const u64* cf = g_u + 48;
        cnot01(R, I, t != 0);
        cnot_ring_mid(R, I);

        // q0 gate (cross-thread, partner xor 1) with C45+C50 folded via
        // lane-mixed packed coefficients. t=1 flips ai and br: per-coef
        // single-lane sign masks.
        {
            u64 mh = t ? SHI : 0ULL, ml = t ? SLO : 0ULL;
            u64 cLR = cf[0] ^ mh;   // (ar, br^s)
            u64 cLI = cf[1] ^ ml;   // (-(ai^s), -bi)
            u64 cMR = cf[2] ^ ml;   // (br^s, ar)
            u64 cMI = cf[3] ^ mh;   // (-bi, -(ai^s))
            u64 dLR = cf[4] ^ ml;   // (ai^s, bi)
            u64 dMR = cf[5] ^ mh;   // (bi, ai^s)
#pragma unroll
            for (int p = 0; p < 16; p++) {
                u64 LR = R[p], LI = I[p];
                u64 MR = __shfl_xor_sync(0xffffffffu, LR, 1);
                u64 MI = __shfl_xor_sync(0xffffffffu, LI, 1);
                if (p & 1) {  // q4=1: C45 lane-swap on all inputs
                    LR = f2swap(LR); LI = f2swap(LI);
                    MR = f2swap(MR); MI = f2swap(MI);
                }
                R[p] = f2fma(cMI, MI, f2fma(cMR, MR, f2fma(cLI, LI, f2mul(cLR, LR))));
                I[p] = f2fma(cMR, MI, f2fma(dMR, MR, f2fma(cLR, LI, f2mul(dLR, LR))));
            }
        }

        su2_loc<8>(R, I, cf + 8);   // q1 (bit3)
        su2_loc<4>(R, I, cf + 16);  // q2 (bit2)
        su2_loc<2>(R, I, cf + 24);  // q3 (bit1)
        su2_loc<1>(R, I, cf + 32);  // q4 (bit0)
        su2_q5(R, I, cf + 40);      // q5 (lane)
    }

    // --- layer-3 prefix: C01 SEL + C12/C23/C34 renames; rest absorbed ---
    cnot01(R, I, t != 0);
    cnot_ring_mid(R, I);

    // --- measurements ---
    float sZ1, sZ2, sZ3, sZ4, sZ45;
    float sEx1, sEy1, sEx2, sEy2, sEx3, sEy3, sX45, sY45;
    {
        u64 az1 = 0, az2 = 0, az3 = 0, az4 = 0;
        u64 ex1 = 0, ey1 = 0, ex2 = 0, ey2 = 0, ex3 = 0, ey3 = 0;
        u64 x45 = 0, y45 = 0;
#pragma unroll
        for (int p = 0; p < 16; p++) {
            u64 pr = f2fma(I[p], I[p], f2mul(R[p], R[p]));
            az1 = f2add(az1, (p & 8) ? (pr ^ SGN2) : pr);
            az2 = f2add(az2, (p & 4) ? (pr ^ SGN2) : pr);
            az3 = f2add(az3, (p & 2) ? (pr ^ SGN2) : pr);
            az4 = f2add(az4, (p & 1) ? (pr ^ SGN2) : pr);
            if (!(p & 8)) {
                ex1 = f2fma(R[p], R[p | 8], f2fma(I[p], I[p | 8], ex1));
                ey1 = f2fma(R[p], I[p | 8], f2fma(I[p] ^ SGN2, R[p | 8], ey1));
            }
            if (!(p & 4)) {
                ex2 = f2fma(R[p], R[p | 4], f2fma(I[p], I[p | 4], ex2));
                ey2 = f2fma(R[p], I[p | 4], f2fma(I[p] ^ SGN2, R[p | 4], ey2));
            }
            if (!(p & 2)) {
                ex3 = f2fma(R[p], R[p | 2], f2fma(I[p], I[p | 2], ex3));
                ey3 = f2fma(R[p], I[p | 2], f2fma(I[p] ^ SGN2, R[p | 2], ey3));
            }
            if (!(p & 1)) {  // single-sided (2x folded into g_m for q4)
                x45 = f2fma(R[p], f2swap(R[p | 1]), f2fma(I[p], f2swap(I[p | 1]), x45));
                y45 = f2fma(R[p], f2swap(I[p | 1]),
                            f2fma(I[p] ^ SGN2, f2swap(R[p | 1]), y45));
            }
        }
        float lo, hi;
        upk2(az1, lo, hi); sZ1  = lo + hi;
        upk2(az2, lo, hi); sZ2  = lo + hi;
        upk2(az3, lo, hi); sZ3  = lo + hi;
        upk2(az4, lo, hi); sZ4  = lo + hi; sZ45 = lo - hi;
        upk2(ex1, lo, hi); sEx1 = lo + hi;
        upk2(ey1, lo, hi); sEy1 = lo + hi;
        upk2(ex2, lo, hi); sEx2 = lo + hi;
        upk2(ey2, lo, hi); sEy2 = lo + hi;
        upk2(ex3, lo, hi); sEx3 = lo + hi;
        upk2(ey3, lo, hi); sEy3 = lo + hi;
        upk2(x45, lo, hi); sX45 = lo + hi;
        upk2(y45, lo, hi); sY45 = lo + hi;
    }

    // cross-thread q0 observables (partner = lane xor 1)
    float sX0, sZY0, sX50, sZYX;
    {
        u64 ax0 = 0, zy0 = 0, x50 = 0, zyx = 0;
#pragma unroll
        for (int p = 0; p < 16; p++) {
            u64 PR = __shfl_xor_sync(0xffffffffu, R[p], 1);
            u64 PI = __shfl_xor_sync(0xffffffffu, I[p], 1);
            ax0 = f2fma(R[p], PR, f2fma(I[p], PI, ax0));
            {
                u64 v = f2fma(R[p], PI, f2mul(I[p] ^ SGN2, PR));
                zy0 = f2add(zy0, (p & 1) ? (v ^ SGN2) : v);
            }
            x50 = f2fma(R[p], f2swap(PR), f2fma(I[p], f2swap(PI), x50));
            {
                u64 v = f2fma(R[p], f2swap(PI), f2mul(I[p] ^ SGN2, f2swap(PR)));
                zyx = f2add(zyx, (p & 1) ? (v ^ SGN2) : v);
            }
        }
        float lo, hi;
        upk2(ax0, lo, hi); sX0  = lo + hi;
        upk2(zy0, lo, hi); sZY0 = lo - hi;
        upk2(x50, lo, hi); sX50 = lo + hi;
        upk2(zyx, lo, hi); sZYX = lo - hi;
    }

    float sgT = t ? -1.0f : 1.0f;  // q0 role sign (q0 = thread bit)

    float m0 = g_m[2]  * (sgT * sZ45) + g_m[0]  * sX0  + g_m[1]  * (sgT * sZY0);
    float m1 = g_m[6]  * sZ1          + g_m[4]  * sEx1 + g_m[5]  * sEy1;
    float m2 = g_m[10] * sZ2          + g_m[8]  * sEx2 + g_m[9]  * sEy2;
    float m3 = g_m[14] * sZ3          + g_m[12] * sEx3 + g_m[13] * sEy3;
    float m4 = g_m[18] * sZ4          + g_m[16] * sX45 + g_m[17] * sY45;
    float m5 = g_m[22] * sZ45         + g_m[20] * sX50 + g_m[21] * sZYX;

    // reduce across the 2-thread group
    m0 += __shfl_xor_sync(0xffffffffu, m0, 1);
    m1 += __shfl_xor_sync(0xffffffffu, m1, 1);
    m2 += __shfl_xor_sync(0xffffffffu, m2, 1);
    m3 += __shfl_xor_sync(0xffffffffu, m3, 1);
    m4 += __shfl_xor_sync(0xffffffffu, m4, 1);
    m5 += __shfl_xor_sync(0xffffffffu, m5, 1);

    if (t == 0) {
        float4* o4 = reinterpret_cast<float4*>(out) + (long)st * 2;
        o4[0] = make_float4(m0, m1, m2, m3);
        o4[1] = make_float4(m4, m5, m0, m1);
    }
}

extern "C" void kernel_launch(void* const* d_in, const int* in_sizes, int n_in,
                              void* d_out, int out_size) {
    const float* x     = (const float*)d_in[0];
    const float* theta = (const float*)d_in[1];
    float* out = (float*)d_out;
    int Bn = in_sizes[0] / 24;

    prep_kernel<<<1, 32>>>(theta);
    long threads = 2L * Bn;
    int blocks = (int)((threads + 127) / 128);
    qsim_kernel<<<blocks, 128>>>(x, out, Bn);
}